// round 9
// baseline (speedup 1.0000x reference)
#include <cuda_runtime.h>
#include <cstdint>

#define GRID       444      // 3 CTAs/SM x 148 SMs (smem-limited), single wave
#define NCOMPUTE   256
#define NTHREADS   288      // 8 consumer warps + 1 producer warp
#define DEPTH      3
#define STAGE_FLOATS 3072u                       // per tensor; 3072 % 6 == 0
#define STAGE_BYTES  (STAGE_FLOATS * 4u)         // 12288
#define SLOT_FLOATS  (2u * STAGE_FLOATS)         // pred + target
#define SLOT_BYTES   (2u * STAGE_BYTES)          // 24576
#define SMEM_BYTES   (DEPTH * SLOT_BYTES)        // 73728 dynamic smem

__device__ float        g_ptot[GRID];
__device__ float        g_prs[GRID];
__device__ unsigned int g_ctr = 0;

#define PI_F  3.14159265358979323846f
#define TPI_F 6.28318530717958647692f

__device__ __forceinline__ float wrap_corr(float x) {
    return (fabsf(x) > PI_F) ? -copysignf(TPI_F, x) : 0.0f;
}

__device__ __forceinline__ uint32_t smem_u32(const void* p) {
    return (uint32_t)__cvta_generic_to_shared(p);
}
__device__ __forceinline__ void mbar_init(uint32_t m, uint32_t cnt) {
    asm volatile("mbarrier.init.shared.b64 [%0], %1;" :: "r"(m), "r"(cnt) : "memory");
}
__device__ __forceinline__ void mbar_expect_tx(uint32_t m, uint32_t bytes) {
    asm volatile("mbarrier.arrive.expect_tx.shared.b64 _, [%0], %1;"
                 :: "r"(m), "r"(bytes) : "memory");
}
__device__ __forceinline__ void mbar_arrive(uint32_t m) {
    asm volatile("mbarrier.arrive.shared.b64 _, [%0];" :: "r"(m) : "memory");
}
__device__ __forceinline__ void mbar_wait_acq(uint32_t m, uint32_t parity) {
    asm volatile(
        "{\n\t.reg .pred P;\n"
        "W_%=:\n\t"
        "mbarrier.try_wait.parity.acquire.cta.shared::cta.b64 P, [%0], %1, 0x989680;\n\t"
        "@P bra D_%=;\n\t"
        "bra W_%=;\n"
        "D_%=:\n\t}"
        :: "r"(m), "r"(parity) : "memory");
}
__device__ __forceinline__ void mbar_wait_rlx(uint32_t m, uint32_t parity) {
    // relaxed: safe here — post-wait smem access is async-proxy (bulk copy) only
    asm volatile(
        "{\n\t.reg .pred P;\n"
        "W_%=:\n\t"
        "mbarrier.try_wait.parity.relaxed.cta.shared::cta.b64 P, [%0], %1, 0x989680;\n\t"
        "@P bra D_%=;\n\t"
        "bra W_%=;\n"
        "D_%=:\n\t}"
        :: "r"(m), "r"(parity) : "memory");
}
__device__ __forceinline__ void bulk_ld(uint32_t dst, const void* src,
                                        uint32_t bytes, uint32_t mbar) {
    asm volatile(
        "cp.async.bulk.shared::cluster.global.mbarrier::complete_tx::bytes "
        "[%0], [%1], %2, [%3];"
        :: "r"(dst), "l"(src), "r"(bytes), "r"(mbar) : "memory");
}

extern __shared__ float s_data[];   // DEPTH x [pred 3072 | target 3072]

// weights for float4 class c (= float4_index % 3):
//   c=0 -> channels {0,1,2,3} -> rot lanes (0,0,0,1)
//   c=1 -> channels {4,5,0,1} -> rot lanes (1,1,0,0)
//   c=2 -> channels {2,3,4,5} -> rot lanes (0,1,1,1)
__device__ __forceinline__ void class_w(unsigned c, float& wx, float& wy,
                                        float& wz, float& ww) {
    wx = (c == 1u) ? 1.0f : 0.0f;
    wy = (c != 0u) ? 1.0f : 0.0f;
    wz = (c == 2u) ? 1.0f : 0.0f;
    ww = (c != 1u) ? 1.0f : 0.0f;
}

__device__ __forceinline__ void accum4(float4 P, float4 T,
                                       float wx, float wy, float wz, float ww,
                                       float& tot, float& rs) {
    float d, cd, v, q;
    d = P.x - T.x; cd = wrap_corr(P.x) - wrap_corr(T.x);
    v = fmaf(wx, cd, d); q = v * v; tot += q; rs = fmaf(q, wx, rs);
    d = P.y - T.y; cd = wrap_corr(P.y) - wrap_corr(T.y);
    v = fmaf(wy, cd, d); q = v * v; tot += q; rs = fmaf(q, wy, rs);
    d = P.z - T.z; cd = wrap_corr(P.z) - wrap_corr(T.z);
    v = fmaf(wz, cd, d); q = v * v; tot += q; rs = fmaf(q, wz, rs);
    d = P.w - T.w; cd = wrap_corr(P.w) - wrap_corr(T.w);
    v = fmaf(ww, cd, d); q = v * v; tot += q; rs = fmaf(q, ww, rs);
}

__global__ void __launch_bounds__(NTHREADS)
wmse_kernel(const float* __restrict__ pf, const float* __restrict__ tf,
            unsigned n, float* __restrict__ out) {
    __shared__ __align__(8) unsigned long long s_full[DEPTH];
    __shared__ __align__(8) unsigned long long s_empty[DEPTH];
    __shared__ float s_rt[NTHREADS / 32];
    __shared__ float s_rr[NTHREADS / 32];
    __shared__ bool  s_isLast;

    const unsigned tid     = threadIdx.x;
    const unsigned nstages = n / STAGE_FLOATS;
    const uint32_t data0   = smem_u32(s_data);
    const uint32_t full0   = smem_u32(&s_full[0]);
    const uint32_t empty0  = smem_u32(&s_empty[0]);

    if (tid == 0) {
        #pragma unroll
        for (int i = 0; i < DEPTH; i++) {
            mbar_init(full0  + 8u * i, 1);         // producer's expect_tx arrival
            mbar_init(empty0 + 8u * i, NCOMPUTE);  // all consumers arrive
        }
    }
    __syncthreads();

    float tot = 0.0f, rs = 0.0f;

    if (tid == NCOMPUTE) {
        // ---- producer (single thread of warp 8) ----
        unsigned local = 0, phase = 1;   // phase=1: first DEPTH empty-waits pass
        for (unsigned s = blockIdx.x; s < nstages; s += GRID, local++) {
            unsigned slot = local % DEPTH;
            mbar_wait_rlx(empty0 + 8u * slot, phase);
            uint32_t dst = data0 + slot * SLOT_BYTES;
            mbar_expect_tx(full0 + 8u * slot, SLOT_BYTES);
            bulk_ld(dst,               pf + (size_t)s * STAGE_FLOATS,
                    STAGE_BYTES, full0 + 8u * slot);
            bulk_ld(dst + STAGE_BYTES, tf + (size_t)s * STAGE_FLOATS,
                    STAGE_BYTES, full0 + 8u * slot);
            if (slot == DEPTH - 1) phase ^= 1;
        }
    } else if (tid < NCOMPUTE) {
        // ---- consumer ----
        // classes of this thread's three float4s: (tid+j) % 3, j = 0,1,2
        unsigned cA = tid % 3u;
        unsigned cB = (cA + 1u) % 3u;
        unsigned cC = (cA + 2u) % 3u;
        float wAx, wAy, wAz, wAw; class_w(cA, wAx, wAy, wAz, wAw);
        float wBx, wBy, wBz, wBw; class_w(cB, wBx, wBy, wBz, wBw);
        float wCx, wCy, wCz, wCw; class_w(cC, wCx, wCy, wCz, wCw);

        unsigned local = 0, phase = 0;
        for (unsigned s = blockIdx.x; s < nstages; s += GRID, local++) {
            unsigned slot = local % DEPTH;
            mbar_wait_acq(full0 + 8u * slot, phase);

            const float4* sp = reinterpret_cast<const float4*>(
                s_data + (size_t)slot * SLOT_FLOATS);         // pred float4s
            const float4* st = sp + (STAGE_FLOATS / 4u);      // target float4s

            float4 P0 = sp[tid];          float4 T0 = st[tid];
            float4 P1 = sp[tid + 256u];   float4 T1 = st[tid + 256u];
            float4 P2 = sp[tid + 512u];   float4 T2 = st[tid + 512u];

            accum4(P0, T0, wAx, wAy, wAz, wAw, tot, rs);
            accum4(P1, T1, wBx, wBy, wBz, wBw, tot, rs);
            accum4(P2, T2, wCx, wCy, wCz, wCw, tot, rs);

            mbar_arrive(empty0 + 8u * slot);
            if (slot == DEPTH - 1) phase ^= 1;
        }

        // remainder floats (n % STAGE_FLOATS), block 0 consumers, from global
        if (blockIdx.x == 0) {
            for (unsigned f = nstages * STAGE_FLOATS + tid; f < n; f += NCOMPUTE) {
                unsigned ch = f % 6u;
                float d  = pf[f] - tf[f];
                float cd = wrap_corr(pf[f]) - wrap_corr(tf[f]);
                float v  = (ch >= 3u) ? (d + cd) : d;
                float q  = v * v;
                tot += q;
                if (ch >= 3u) rs += q;
            }
        }
    }

    // ---- block reduction over all 288 threads (producer warp adds zeros) ----
    #pragma unroll
    for (int o = 16; o > 0; o >>= 1) {
        tot += __shfl_xor_sync(0xffffffffu, tot, o);
        rs  += __shfl_xor_sync(0xffffffffu, rs, o);
    }
    int lane = threadIdx.x & 31;
    int warp = threadIdx.x >> 5;
    if (lane == 0) { s_rt[warp] = tot; s_rr[warp] = rs; }
    __syncthreads();

    if (tid == 0) {
        float bt = 0.0f, br = 0.0f;
        #pragma unroll
        for (int w = 0; w < NTHREADS / 32; w++) { bt += s_rt[w]; br += s_rr[w]; }
        g_ptot[blockIdx.x] = bt;
        g_prs[blockIdx.x]  = br;
        __threadfence();
        unsigned prev = atomicAdd(&g_ctr, 1u);
        s_isLast = (prev == (unsigned)GRID - 1u);
    }
    __syncthreads();

    if (s_isLast) {
        __threadfence();
        float a = 0.0f, b = 0.0f;
        for (unsigned i = tid; i < GRID; i += NTHREADS) {
            a += g_ptot[i];
            b += g_prs[i];
        }
        #pragma unroll
        for (int o = 16; o > 0; o >>= 1) {
            a += __shfl_xor_sync(0xffffffffu, a, o);
            b += __shfl_xor_sync(0xffffffffu, b, o);
        }
        __syncthreads();
        if (lane == 0) { s_rt[warp] = a; s_rr[warp] = b; }
        __syncthreads();
        if (tid == 0) {
            float A = 0.0f, B = 0.0f;
            #pragma unroll
            for (int w = 0; w < NTHREADS / 32; w++) { A += s_rt[w]; B += s_rr[w]; }
            g_ctr = 0;                               // rearm for next replay
            double cnt        = (double)n * 0.5;     // elements per class
            double rot_sum    = (double)B;
            double trans_sum  = (double)A - rot_sum;
            double trans_loss = trans_sum / cnt;             // TRANS_WEIGHT=1
            double rot_loss   = (rot_sum / cnt) * 100.0;     // ROT_WEIGHT=100
            out[0] = (float)(trans_loss + rot_loss);
            out[1] = (float)trans_loss;
            out[2] = (float)rot_loss;
        }
    }
}

extern "C" void kernel_launch(void* const* d_in, const int* in_sizes, int n_in,
                              void* d_out, int out_size) {
    const float* pred   = (const float*)d_in[0];
    const float* target = (const float*)d_in[1];
    unsigned n = (unsigned)in_sizes[0];

    // Idempotent attribute set (dynamic smem > 48 KB); host-side, no allocation.
    cudaFuncSetAttribute(wmse_kernel,
                         cudaFuncAttributeMaxDynamicSharedMemorySize, SMEM_BYTES);

    wmse_kernel<<<GRID, NTHREADS, SMEM_BYTES>>>(pred, target, n, (float*)d_out);
}

// round 11
// speedup vs baseline: 1.0927x; 1.0927x over previous
#include <cuda_runtime.h>
#include <cstdint>

#define NBLOCKS  444
#define NTHREADS 384
// 444 = 3 CTAs/SM x 148 SMs at 384 threads -> 1152 thr/SM, single balanced wave.
// Register budget 65536/1152 = 56 regs/thread: fits TWO 8-float load buffers
// (32 data regs) + 8 weights -> true software pipelining, no WAR serialization.
// total = 170,496 threads, divisible by 3 -> chunk%3 loop-invariant per thread.

__device__ float        g_ptot[NBLOCKS];
__device__ float        g_prs[NBLOCKS];
__device__ unsigned int g_ctr = 0;   // reset by the last block each call

#define PI_F  3.14159265358979323846f
#define TPI_F 6.28318530717958647692f

__device__ __forceinline__ float wrap_corr(float x) {
    return (fabsf(x) > PI_F) ? -copysignf(TPI_F, x) : 0.0f;
}

// Blackwell 256-bit global load: 8 consecutive floats per thread.
__device__ __forceinline__ void ldg256(const float* __restrict__ p, float* r) {
    asm("ld.global.nc.v8.f32 {%0,%1,%2,%3,%4,%5,%6,%7}, [%8];"
        : "=f"(r[0]), "=f"(r[1]), "=f"(r[2]), "=f"(r[3]),
          "=f"(r[4]), "=f"(r[5]), "=f"(r[6]), "=f"(r[7])
        : "l"(p));
}

__device__ __forceinline__ void accum8(const float* P, const float* T,
                                       const float* w, float& tot, float& rs) {
    #pragma unroll
    for (int i = 0; i < 8; i++) {
        float d  = P[i] - T[i];
        float cd = wrap_corr(P[i]) - wrap_corr(T[i]);
        float v  = fmaf(w[i], cd, d);   // trans: d, rot: wrapped diff
        float q  = v * v;
        tot += q;
        rs  = fmaf(q, w[i], rs);
    }
}

__global__ void __launch_bounds__(NTHREADS, 3)
wmse_kernel(const float* __restrict__ pf, const float* __restrict__ tf,
            unsigned n, float* __restrict__ out) {
    const unsigned total = NBLOCKS * NTHREADS;     // divisible by 3
    const unsigned tid   = blockIdx.x * NTHREADS + threadIdx.x;
    const unsigned n8    = n / 8u;                 // 8-float chunks

    // Channels of chunk u are (8u..8u+7) mod 6; pattern depends only on
    // u % 3 == tid % 3 (stride divisible by 3):
    //   m=0 -> rot lanes {3,4,5}; m=1 -> {1,2,3,7}; m=2 -> {0,1,5,6,7}
    const unsigned m = tid % 3u;
    float w[8];
    w[0] = (m == 2u) ? 1.0f : 0.0f;
    w[1] = (m != 0u) ? 1.0f : 0.0f;
    w[2] = (m == 1u) ? 1.0f : 0.0f;
    w[3] = (m != 2u) ? 1.0f : 0.0f;
    w[4] = (m == 0u) ? 1.0f : 0.0f;
    w[5] = (m != 1u) ? 1.0f : 0.0f;
    w[6] = (m == 2u) ? 1.0f : 0.0f;
    w[7] = (m != 0u) ? 1.0f : 0.0f;

    float tot = 0.0f;   // sum of val^2 over ALL lanes
    float rs  = 0.0f;   // sum of val^2 over rotation lanes only

    // Two-buffer software-pipelined mainloop: next iteration's loads are
    // issued BEFORE the current iteration's compute, in distinct registers.
    float PA[8], TA[8], PB[8], TB[8];
    unsigned u = tid;
    if (u < n8) {
        ldg256(pf + (size_t)u * 8u, PA);
        ldg256(tf + (size_t)u * 8u, TA);
        for (;;) {
            unsigned u1 = u + total;
            if (u1 < n8) {
                ldg256(pf + (size_t)u1 * 8u, PB);      // prefetch into B
                ldg256(tf + (size_t)u1 * 8u, TB);
                accum8(PA, TA, w, tot, rs);            // consume A
                unsigned u2 = u1 + total;
                if (u2 < n8) {
                    ldg256(pf + (size_t)u2 * 8u, PA);  // prefetch into A
                    ldg256(tf + (size_t)u2 * 8u, TA);
                    accum8(PB, TB, w, tot, rs);        // consume B
                    u = u2;
                    continue;
                }
                accum8(PB, TB, w, tot, rs);
                break;
            }
            accum8(PA, TA, w, tot, rs);
            break;
        }
    }

    // Generic tail: floats beyond the last full 8-chunk (empty for bench shape).
    if (tid == 0) {
        for (unsigned f = n8 * 8u; f < n; f++) {
            unsigned c = f % 6u;
            float d  = pf[f] - tf[f];
            float cd = wrap_corr(pf[f]) - wrap_corr(tf[f]);
            float v  = (c >= 3u) ? (d + cd) : d;
            float q  = v * v;
            tot += q;
            if (c >= 3u) rs += q;
        }
    }

    // Block reduction of (tot, rs)
    #pragma unroll
    for (int o = 16; o > 0; o >>= 1) {
        tot += __shfl_xor_sync(0xffffffffu, tot, o);
        rs  += __shfl_xor_sync(0xffffffffu, rs, o);
    }
    __shared__ float stot[NTHREADS / 32];
    __shared__ float srs[NTHREADS / 32];
    int lane = threadIdx.x & 31;
    int warp = threadIdx.x >> 5;
    if (lane == 0) { stot[warp] = tot; srs[warp] = rs; }
    __syncthreads();

    __shared__ bool isLast;
    if (threadIdx.x == 0) {
        float btot = 0.0f, brs = 0.0f;
        #pragma unroll
        for (int ww = 0; ww < NTHREADS / 32; ww++) { btot += stot[ww]; brs += srs[ww]; }
        g_ptot[blockIdx.x] = btot;
        g_prs[blockIdx.x]  = brs;
        __threadfence();
        unsigned prev = atomicAdd(&g_ctr, 1u);
        isLast = (prev == (unsigned)gridDim.x - 1u);
    }
    __syncthreads();

    if (isLast) {
        __threadfence();
        float a = 0.0f, b = 0.0f;
        for (unsigned i = threadIdx.x; i < NBLOCKS; i += NTHREADS) {
            a += g_ptot[i];
            b += g_prs[i];
        }
        #pragma unroll
        for (int o = 16; o > 0; o >>= 1) {
            a += __shfl_xor_sync(0xffffffffu, a, o);
            b += __shfl_xor_sync(0xffffffffu, b, o);
        }
        __syncthreads();                 // stot/srs reuse
        if (lane == 0) { stot[warp] = a; srs[warp] = b; }
        __syncthreads();
        if (threadIdx.x == 0) {
            float A = 0.0f, B = 0.0f;    // A = tot sum, B = rot sum
            #pragma unroll
            for (int ww = 0; ww < NTHREADS / 32; ww++) { A += stot[ww]; B += srs[ww]; }
            g_ctr = 0;                   // rearm for the next graph replay
            double cnt        = (double)n * 0.5;             // elems / 2
            double rot_sum    = (double)B;
            double trans_sum  = (double)A - rot_sum;         // tot - rot
            double trans_loss = trans_sum / cnt;             // TRANS_WEIGHT=1
            double rot_loss   = (rot_sum / cnt) * 100.0;     // ROT_WEIGHT=100
            out[0] = (float)(trans_loss + rot_loss);
            out[1] = (float)trans_loss;
            out[2] = (float)rot_loss;
        }
    }
}

extern "C" void kernel_launch(void* const* d_in, const int* in_sizes, int n_in,
                              void* d_out, int out_size) {
    const float* pred   = (const float*)d_in[0];
    const float* target = (const float*)d_in[1];
    unsigned n = (unsigned)in_sizes[0];

    wmse_kernel<<<NBLOCKS, NTHREADS>>>(pred, target, n, (float*)d_out);
}

// round 12
// speedup vs baseline: 1.0946x; 1.0017x over previous
#include <cuda_runtime.h>
#include <cstdint>

#define NBLOCKS  296
#define NTHREADS 384
// 296 = 2 CTAs/SM x 148 SMs at 384 threads -> 768 thr/SM, single wave.
// Register budget 65536/768 = 85 regs/thread: fits THREE 16-float buffer pairs
// (48 data regs) -> depth-3 pipeline, >=1 buffer pair in flight at all times.
// total = 113,664 threads, divisible by 3 -> chunk%3 loop-invariant per thread.

__device__ float        g_ptot[NBLOCKS];
__device__ float        g_prs[NBLOCKS];
__device__ unsigned int g_ctr = 0;   // reset by the last block each call

#define PI_F  3.14159265358979323846f
#define TPI_F 6.28318530717958647692f

__device__ __forceinline__ float wrap_corr(float x) {
    return (fabsf(x) > PI_F) ? -copysignf(TPI_F, x) : 0.0f;
}

// Blackwell 256-bit global load: 8 consecutive floats per thread.
__device__ __forceinline__ void ldg256(const float* __restrict__ p, float* r) {
    asm("ld.global.nc.v8.f32 {%0,%1,%2,%3,%4,%5,%6,%7}, [%8];"
        : "=f"(r[0]), "=f"(r[1]), "=f"(r[2]), "=f"(r[3]),
          "=f"(r[4]), "=f"(r[5]), "=f"(r[6]), "=f"(r[7])
        : "l"(p));
}

__device__ __forceinline__ void accum8(const float* P, const float* T,
                                       const float* w, float& tot, float& rs) {
    #pragma unroll
    for (int i = 0; i < 8; i++) {
        float d  = P[i] - T[i];
        float cd = wrap_corr(P[i]) - wrap_corr(T[i]);
        float v  = fmaf(w[i], cd, d);   // trans: d, rot: wrapped diff
        float q  = v * v;
        tot += q;
        rs  = fmaf(q, w[i], rs);
    }
}

__global__ void __launch_bounds__(NTHREADS, 2)
wmse_kernel(const float* __restrict__ pf, const float* __restrict__ tf,
            unsigned n, float* __restrict__ out) {
    const unsigned total = NBLOCKS * NTHREADS;     // divisible by 3
    const unsigned tid   = blockIdx.x * NTHREADS + threadIdx.x;
    const unsigned n8    = n / 8u;                 // 8-float chunks

    // Channels of chunk u: pattern depends only on u % 3 == tid % 3:
    //   m=0 -> rot lanes {3,4,5}; m=1 -> {1,2,3,7}; m=2 -> {0,1,5,6,7}
    const unsigned m = tid % 3u;
    float w[8];
    w[0] = (m == 2u) ? 1.0f : 0.0f;
    w[1] = (m != 0u) ? 1.0f : 0.0f;
    w[2] = (m == 1u) ? 1.0f : 0.0f;
    w[3] = (m != 2u) ? 1.0f : 0.0f;
    w[4] = (m == 0u) ? 1.0f : 0.0f;
    w[5] = (m != 1u) ? 1.0f : 0.0f;
    w[6] = (m == 2u) ? 1.0f : 0.0f;
    w[7] = (m != 0u) ? 1.0f : 0.0f;

    float tot = 0.0f;   // sum of val^2 over ALL lanes
    float rs  = 0.0f;   // sum of val^2 over rotation lanes only

    // Uniform full iterations for every thread, floored to a multiple of 3 so
    // the depth-3 rotation needs NO bounds checks inside the mainloop.
    const unsigned iters  = n8 / total;
    const unsigned iters3 = iters - (iters % 3u);   // 27 for the bench shape

    float P0[8], T0[8], P1[8], T1[8], P2[8], T2[8];
    unsigned u = tid;

    if (iters3 >= 3u) {
        ldg256(pf + (size_t)u * 8u, P0);
        ldg256(tf + (size_t)u * 8u, T0);
        ldg256(pf + (size_t)(u + total) * 8u, P1);
        ldg256(tf + (size_t)(u + total) * 8u, T1);

        for (unsigned k = 3u; k < iters3; k += 3u) {
            ldg256(pf + (size_t)(u + 2u * total) * 8u, P2);
            ldg256(tf + (size_t)(u + 2u * total) * 8u, T2);
            accum8(P0, T0, w, tot, rs);
            ldg256(pf + (size_t)(u + 3u * total) * 8u, P0);
            ldg256(tf + (size_t)(u + 3u * total) * 8u, T0);
            accum8(P1, T1, w, tot, rs);
            ldg256(pf + (size_t)(u + 4u * total) * 8u, P1);
            ldg256(tf + (size_t)(u + 4u * total) * 8u, T1);
            accum8(P2, T2, w, tot, rs);
            u += 3u * total;
        }
        // Final group: P0/P1 already resident; fetch its third chunk.
        ldg256(pf + (size_t)(u + 2u * total) * 8u, P2);
        ldg256(tf + (size_t)(u + 2u * total) * 8u, T2);
        accum8(P0, T0, w, tot, rs);
        accum8(P1, T1, w, tot, rs);
        accum8(P2, T2, w, tot, rs);
        u += 3u * total;
    }

    // Epilogue: leftover full chunks (iters % 3 rounds + ragged extra chunk).
    for (; u < n8; u += total) {
        ldg256(pf + (size_t)u * 8u, P0);
        ldg256(tf + (size_t)u * 8u, T0);
        accum8(P0, T0, w, tot, rs);
    }

    // Generic tail: floats beyond the last full 8-chunk (empty for bench shape).
    if (tid == 0) {
        for (unsigned f = n8 * 8u; f < n; f++) {
            unsigned c = f % 6u;
            float d  = pf[f] - tf[f];
            float cd = wrap_corr(pf[f]) - wrap_corr(tf[f]);
            float v  = (c >= 3u) ? (d + cd) : d;
            float q  = v * v;
            tot += q;
            if (c >= 3u) rs += q;
        }
    }

    // Block reduction of (tot, rs)
    #pragma unroll
    for (int o = 16; o > 0; o >>= 1) {
        tot += __shfl_xor_sync(0xffffffffu, tot, o);
        rs  += __shfl_xor_sync(0xffffffffu, rs, o);
    }
    __shared__ float stot[NTHREADS / 32];
    __shared__ float srs[NTHREADS / 32];
    int lane = threadIdx.x & 31;
    int warp = threadIdx.x >> 5;
    if (lane == 0) { stot[warp] = tot; srs[warp] = rs; }
    __syncthreads();

    __shared__ bool isLast;
    if (threadIdx.x == 0) {
        float btot = 0.0f, brs = 0.0f;
        #pragma unroll
        for (int ww = 0; ww < NTHREADS / 32; ww++) { btot += stot[ww]; brs += srs[ww]; }
        g_ptot[blockIdx.x] = btot;
        g_prs[blockIdx.x]  = brs;
        __threadfence();
        unsigned prev = atomicAdd(&g_ctr, 1u);
        isLast = (prev == (unsigned)gridDim.x - 1u);
    }
    __syncthreads();

    if (isLast) {
        __threadfence();
        float a = 0.0f, b = 0.0f;
        for (unsigned i = threadIdx.x; i < NBLOCKS; i += NTHREADS) {
            a += g_ptot[i];
            b += g_prs[i];
        }
        #pragma unroll
        for (int o = 16; o > 0; o >>= 1) {
            a += __shfl_xor_sync(0xffffffffu, a, o);
            b += __shfl_xor_sync(0xffffffffu, b, o);
        }
        __syncthreads();                 // stot/srs reuse
        if (lane == 0) { stot[warp] = a; srs[warp] = b; }
        __syncthreads();
        if (threadIdx.x == 0) {
            float A = 0.0f, B = 0.0f;    // A = tot sum, B = rot sum
            #pragma unroll
            for (int ww = 0; ww < NTHREADS / 32; ww++) { A += stot[ww]; B += srs[ww]; }
            g_ctr = 0;                   // rearm for the next graph replay
            double cnt        = (double)n * 0.5;             // elems / 2
            double rot_sum    = (double)B;
            double trans_sum  = (double)A - rot_sum;         // tot - rot
            double trans_loss = trans_sum / cnt;             // TRANS_WEIGHT=1
            double rot_loss   = (rot_sum / cnt) * 100.0;     // ROT_WEIGHT=100
            out[0] = (float)(trans_loss + rot_loss);
            out[1] = (float)trans_loss;
            out[2] = (float)rot_loss;
        }
    }
}

extern "C" void kernel_launch(void* const* d_in, const int* in_sizes, int n_in,
                              void* d_out, int out_size) {
    const float* pred   = (const float*)d_in[0];
    const float* target = (const float*)d_in[1];
    unsigned n = (unsigned)in_sizes[0];

    wmse_kernel<<<NBLOCKS, NTHREADS>>>(pred, target, n, (float*)d_out);
}